// round 1
// baseline (speedup 1.0000x reference)
#include <cuda_runtime.h>
#include <cuda_fp16.h>

#define S_LEN 2048
#define B_SZ 2
#define NH 16
#define NKV 4
#define HD 128
#define QSTRIDE (NH*HD)      /* 2048 */
#define KSTRIDE (NKV*HD)     /* 512  */
#define SCALE_F 0.08838834764831845f
#define BQ 64
#define BK 64
#define QP 136               /* Q/K smem pitch in halves: 272B -> 4-bank row shift, conflict-free frag loads */
#define VP 72                /* Vt pitch in halves: 144B -> 4-bank shift */
#define NTS 64               /* NUM_TOKENS_SCORE */

#define SMEM1 ((2*BQ*QP + HD*VP) * 2)                       /* 53248 B */
#define SMEM2 (64*128*2 + 128*130*2 + 2*64*4)               /* 50176 B */

__device__ float g_m[B_SZ*NH*NTS];
__device__ float g_l[B_SZ*NH*NTS];

__device__ __forceinline__ void mma16816(float& c0, float& c1, float& c2, float& c3,
                                         unsigned a0, unsigned a1, unsigned a2, unsigned a3,
                                         unsigned b0, unsigned b1) {
    asm volatile(
        "mma.sync.aligned.m16n8k16.row.col.f32.f16.f16.f32 "
        "{%0,%1,%2,%3}, {%4,%5,%6,%7}, {%8,%9}, {%0,%1,%2,%3};\n"
        : "+f"(c0), "+f"(c1), "+f"(c2), "+f"(c3)
        : "r"(a0), "r"(a1), "r"(a2), "r"(a3), "r"(b0), "r"(b1));
}

__device__ __forceinline__ unsigned pack2(float x, float y) {
    half2 t = __floats2half2_rn(x, y);
    return *reinterpret_cast<unsigned*>(&t);
}

// ---------------------------------------------------------------------------
// Kernel 1: causal flash attention forward (fp16 HMMA, fp32 accum).
// grid (S/BQ, NH, B), 128 threads. Warp w owns query rows [w*16, w*16+16).
// ---------------------------------------------------------------------------
__global__ void __launch_bounds__(128, 1) flash_fwd(
    const float* __restrict__ q, const float* __restrict__ k,
    const float* __restrict__ v, float* __restrict__ out)
{
    extern __shared__ __align__(16) half smem1[];
    half* Qs = smem1;                 // BQ x QP
    half* Ks = smem1 + BQ*QP;         // BK x QP
    half* Vt = smem1 + 2*BQ*QP;       // HD x VP (V transposed: Vt[d][kk])

    const int qi   = blockIdx.x;
    const int h    = blockIdx.y;
    const int b    = blockIdx.z;
    const int hk   = h >> 2;          // rep = 4
    const int tid  = threadIdx.x;
    const int w    = tid >> 5;
    const int lane = tid & 31;
    const int q0   = qi * BQ;

    // ---- load Q tile, folding softmax scale into Q before fp16 rounding ----
    {
        const float* qbase = q + (size_t)(b*S_LEN + q0)*QSTRIDE + h*HD;
        for (int i = tid; i < BQ*32; i += 128) {
            int r = i >> 5, c4 = i & 31;
            float4 qv = *(const float4*)(qbase + (size_t)r*QSTRIDE + c4*4);
            half2* dst = (half2*)&Qs[r*QP + c4*4];
            dst[0] = __floats2half2_rn(qv.x*SCALE_F, qv.y*SCALE_F);
            dst[1] = __floats2half2_rn(qv.z*SCALE_F, qv.w*SCALE_F);
        }
    }

    const int rq   = lane >> 2;          // 0..7
    const int row0 = w*16 + rq;          // local q row (and +8)
    const int cq   = (lane & 3) * 2;

    float m0 = -1e30f, m1 = -1e30f, l0 = 0.f, l1 = 0.f;
    float oacc[16][4];
    #pragma unroll
    for (int nb = 0; nb < 16; nb++) {
        oacc[nb][0] = 0.f; oacc[nb][1] = 0.f; oacc[nb][2] = 0.f; oacc[nb][3] = 0.f;
    }

    for (int jt = 0; jt <= qi; jt++) {
        const int k0 = jt * BK;
        __syncthreads();   // previous iteration's PV smem reads done

        // ---- load K tile (row-major) and V tile (transposed) ----
        {
            const float* kbase = k + (size_t)(b*S_LEN + k0)*KSTRIDE + hk*HD;
            for (int i = tid; i < BK*32; i += 128) {
                int r = i >> 5, c4 = i & 31;
                float4 kv = *(const float4*)(kbase + (size_t)r*KSTRIDE + c4*4);
                half2* dst = (half2*)&Ks[r*QP + c4*4];
                dst[0] = __floats2half2_rn(kv.x, kv.y);
                dst[1] = __floats2half2_rn(kv.z, kv.w);
            }
            const float* vbase = v + (size_t)(b*S_LEN + k0)*KSTRIDE + hk*HD;
            for (int i = tid; i < 1024; i += 128) {
                int d4 = i & 31;   // d chunk (4 floats)
                int kp = i >> 5;   // key pair
                float4 va = *(const float4*)(vbase + (size_t)(2*kp  )*KSTRIDE + d4*4);
                float4 vb = *(const float4*)(vbase + (size_t)(2*kp+1)*KSTRIDE + d4*4);
                *(half2*)&Vt[(d4*4+0)*VP + 2*kp] = __floats2half2_rn(va.x, vb.x);
                *(half2*)&Vt[(d4*4+1)*VP + 2*kp] = __floats2half2_rn(va.y, vb.y);
                *(half2*)&Vt[(d4*4+2)*VP + 2*kp] = __floats2half2_rn(va.z, vb.z);
                *(half2*)&Vt[(d4*4+3)*VP + 2*kp] = __floats2half2_rn(va.w, vb.w);
            }
        }
        __syncthreads();

        // ---- S = Q * K^T (16x64 per warp) ----
        float sacc[8][4];
        #pragma unroll
        for (int nb = 0; nb < 8; nb++) {
            sacc[nb][0] = 0.f; sacc[nb][1] = 0.f; sacc[nb][2] = 0.f; sacc[nb][3] = 0.f;
        }
        #pragma unroll
        for (int kd = 0; kd < 8; kd++) {
            const int dcol = kd*16 + cq;
            unsigned a0 = *(const unsigned*)&Qs[ row0   *QP + dcol];
            unsigned a1 = *(const unsigned*)&Qs[(row0+8)*QP + dcol];
            unsigned a2 = *(const unsigned*)&Qs[ row0   *QP + dcol + 8];
            unsigned a3 = *(const unsigned*)&Qs[(row0+8)*QP + dcol + 8];
            #pragma unroll
            for (int nb = 0; nb < 8; nb++) {
                unsigned b0 = *(const unsigned*)&Ks[(nb*8+rq)*QP + dcol];
                unsigned b1 = *(const unsigned*)&Ks[(nb*8+rq)*QP + dcol + 8];
                mma16816(sacc[nb][0], sacc[nb][1], sacc[nb][2], sacc[nb][3],
                         a0, a1, a2, a3, b0, b1);
            }
        }

        // ---- causal mask (only the diagonal tile; tiles are aligned) ----
        if (jt == qi) {
            #pragma unroll
            for (int nb = 0; nb < 8; nb++) {
                int col = nb*8 + cq;
                if (col     > row0    ) sacc[nb][0] = -1e30f;
                if (col + 1 > row0    ) sacc[nb][1] = -1e30f;
                if (col     > row0 + 8) sacc[nb][2] = -1e30f;
                if (col + 1 > row0 + 8) sacc[nb][3] = -1e30f;
            }
        }

        // ---- online softmax ----
        float mx0 = -1e30f, mx1 = -1e30f;
        #pragma unroll
        for (int nb = 0; nb < 8; nb++) {
            mx0 = fmaxf(mx0, fmaxf(sacc[nb][0], sacc[nb][1]));
            mx1 = fmaxf(mx1, fmaxf(sacc[nb][2], sacc[nb][3]));
        }
        mx0 = fmaxf(mx0, __shfl_xor_sync(0xffffffffu, mx0, 1));
        mx0 = fmaxf(mx0, __shfl_xor_sync(0xffffffffu, mx0, 2));
        mx1 = fmaxf(mx1, __shfl_xor_sync(0xffffffffu, mx1, 1));
        mx1 = fmaxf(mx1, __shfl_xor_sync(0xffffffffu, mx1, 2));

        float mn0 = fmaxf(m0, mx0), mn1 = fmaxf(m1, mx1);
        float al0 = __expf(m0 - mn0), al1 = __expf(m1 - mn1);
        m0 = mn0; m1 = mn1;

        float s0 = 0.f, s1 = 0.f;
        #pragma unroll
        for (int nb = 0; nb < 8; nb++) {
            sacc[nb][0] = __expf(sacc[nb][0] - mn0);
            sacc[nb][1] = __expf(sacc[nb][1] - mn0);
            sacc[nb][2] = __expf(sacc[nb][2] - mn1);
            sacc[nb][3] = __expf(sacc[nb][3] - mn1);
            s0 += sacc[nb][0] + sacc[nb][1];
            s1 += sacc[nb][2] + sacc[nb][3];
        }
        s0 += __shfl_xor_sync(0xffffffffu, s0, 1);
        s0 += __shfl_xor_sync(0xffffffffu, s0, 2);
        s1 += __shfl_xor_sync(0xffffffffu, s1, 1);
        s1 += __shfl_xor_sync(0xffffffffu, s1, 2);
        l0 = l0*al0 + s0;
        l1 = l1*al1 + s1;

        #pragma unroll
        for (int nb = 0; nb < 16; nb++) {
            oacc[nb][0] *= al0; oacc[nb][1] *= al0;
            oacc[nb][2] *= al1; oacc[nb][3] *= al1;
        }

        // ---- O += P * V ----
        #pragma unroll
        for (int kb = 0; kb < 4; kb++) {
            unsigned a0 = pack2(sacc[2*kb  ][0], sacc[2*kb  ][1]);
            unsigned a1 = pack2(sacc[2*kb  ][2], sacc[2*kb  ][3]);
            unsigned a2 = pack2(sacc[2*kb+1][0], sacc[2*kb+1][1]);
            unsigned a3 = pack2(sacc[2*kb+1][2], sacc[2*kb+1][3]);
            const int kcol = kb*16 + cq;
            #pragma unroll
            for (int nb = 0; nb < 16; nb++) {
                unsigned b0 = *(const unsigned*)&Vt[(nb*8+rq)*VP + kcol];
                unsigned b1 = *(const unsigned*)&Vt[(nb*8+rq)*VP + kcol + 8];
                mma16816(oacc[nb][0], oacc[nb][1], oacc[nb][2], oacc[nb][3],
                         a0, a1, a2, a3, b0, b1);
            }
        }
    }

    // ---- epilogue ----
    const float inv0 = 1.0f / l0;
    const float inv1 = 1.0f / l1;
    const int grow0 = q0 + row0;
    const int grow1 = grow0 + 8;
    float* ob0 = out + (size_t)(b*S_LEN + grow0)*QSTRIDE + h*HD;
    float* ob1 = out + (size_t)(b*S_LEN + grow1)*QSTRIDE + h*HD;
    #pragma unroll
    for (int nb = 0; nb < 16; nb++) {
        int col = nb*8 + cq;
        *(float2*)(ob0 + col) = make_float2(oacc[nb][0]*inv0, oacc[nb][1]*inv0);
        *(float2*)(ob1 + col) = make_float2(oacc[nb][2]*inv1, oacc[nb][3]*inv1);
    }

    // stash exact softmax stats for the last NTS query rows
    if (q0 == S_LEN - NTS && (lane & 3) == 0) {
        int base = (b*NH + h)*NTS;
        g_m[base + row0    ] = m0;
        g_m[base + row0 + 8] = m1;
        g_l[base + row0    ] = l0;
        g_l[base + row0 + 8] = l1;
    }
}

// ---------------------------------------------------------------------------
// Kernel 2: score_sum[b,h,k] = sum over last 64 queries q>=k of exp(s-m_q)/l_q.
// Uses identical fp16-rounded (scaled) Q and fp16 K so scores match kernel 1.
// grid (S/128, NH, B), 128 threads; thread t owns key k0+t.
// ---------------------------------------------------------------------------
__global__ void __launch_bounds__(128, 1) score_sum_k(
    const float* __restrict__ qg, const float* __restrict__ kg,
    float* __restrict__ ssum)
{
    extern __shared__ __align__(16) half smem2[];
    half*  qs = smem2;                     // 64 x 128
    half*  ks = smem2 + 64*128;            // 128 x 130 (padded: conflict-free per-thread rows)
    float* ms = (float*)(smem2 + 64*128 + 128*130);
    float* ws = ms + 64;

    const int tid = threadIdx.x;
    const int h   = blockIdx.y;
    const int b   = blockIdx.z;
    const int hk  = h >> 2;
    const int k0  = blockIdx.x * 128;

    // last-64 query rows, scaled, fp16-rounded (same expression as kernel 1)
    for (int i = tid; i < 64*64; i += 128) {
        int r = i >> 6, c2 = i & 63;
        float2 qv = *(const float2*)(qg + (size_t)(b*S_LEN + (S_LEN - NTS) + r)*QSTRIDE + h*HD + c2*2);
        *(half2*)&qs[r*128 + c2*2] = __floats2half2_rn(qv.x*SCALE_F, qv.y*SCALE_F);
    }
    for (int i = tid; i < 128*64; i += 128) {
        int r = i >> 6, c2 = i & 63;
        float2 kv = *(const float2*)(kg + (size_t)(b*S_LEN + k0 + r)*KSTRIDE + hk*HD + c2*2);
        *(half2*)&ks[r*130 + c2*2] = __floats2half2_rn(kv.x, kv.y);
    }
    if (tid < 64) {
        int base = (b*NH + h)*NTS;
        ms[tid] = g_m[base + tid];
        ws[tid] = 1.0f / g_l[base + tid];
    }
    __syncthreads();

    float dot[64];
    #pragma unroll
    for (int qq = 0; qq < 64; qq++) dot[qq] = 0.f;

    for (int c2 = 0; c2 < 64; c2++) {
        float2 kf = __half22float2(*(const half2*)&ks[tid*130 + c2*2]);
        #pragma unroll
        for (int qq = 0; qq < 64; qq++) {
            float2 qf = __half22float2(*(const half2*)&qs[qq*128 + c2*2]);
            dot[qq] += kf.x*qf.x + kf.y*qf.y;
        }
    }

    const int kidx = k0 + tid;
    const int t = kidx - (S_LEN - NTS);   // first q that can see this key (if >0)
    float acc = 0.f;
    #pragma unroll
    for (int qq = 0; qq < 64; qq++) {
        if (qq >= t) acc += __expf(dot[qq] - ms[qq]) * ws[qq];
    }
    ssum[((size_t)b*NH + h)*S_LEN + kidx] = acc;
}

// ---------------------------------------------------------------------------
extern "C" void kernel_launch(void* const* d_in, const int* in_sizes, int n_in,
                              void* d_out, int out_size)
{
    const float* q = (const float*)d_in[0];
    const float* k = (const float*)d_in[1];
    const float* v = (const float*)d_in[2];
    // d_in[3], d_in[4]: batch_size / seq_len scalars (compile-time constants here)

    float* out  = (float*)d_out;
    float* ssum = out + (size_t)B_SZ * S_LEN * QSTRIDE;

    cudaFuncSetAttribute(flash_fwd,   cudaFuncAttributeMaxDynamicSharedMemorySize, SMEM1);
    cudaFuncSetAttribute(score_sum_k, cudaFuncAttributeMaxDynamicSharedMemorySize, SMEM2);

    dim3 g1(S_LEN/BQ, NH, B_SZ);
    flash_fwd<<<g1, 128, SMEM1>>>(q, k, v, out);

    dim3 g2(S_LEN/128, NH, B_SZ);
    score_sum_k<<<g2, 128, SMEM2>>>(q, k, ssum);
}

// round 2
// speedup vs baseline: 2.2662x; 2.2662x over previous
#include <cuda_runtime.h>
#include <cuda_fp16.h>

#define S_LEN 2048
#define B_SZ 2
#define NH 16
#define NKV 4
#define HD 128
#define QSTRIDE (NH*HD)      /* 2048 */
#define KSTRIDE (NKV*HD)     /* 512  */
#define SCALE_F 0.08838834764831845f
#define LOG2E   1.44269504088896341f
#define QSC     (SCALE_F*LOG2E)      /* fold softmax scale + log2e into Q */
#define BQ 128
#define BK 128
#define PIT 136              /* smem pitch in halves: 272B rows -> conflict-free LDSM */
#define NTS 64

#define SMEM1 (5*BK*PIT*2)                              /* Q + 2*(K+V) = 174080 B */
#define SMEM2 ((64+128)*PIT*2 + (64+64+512)*4)          /* 54784 B */

__device__ float g_m[B_SZ*NH*NTS];   // log2-domain row max
__device__ float g_l[B_SZ*NH*NTS];   // row denom

__device__ __forceinline__ void mma16816(float& c0, float& c1, float& c2, float& c3,
                                         unsigned a0, unsigned a1, unsigned a2, unsigned a3,
                                         unsigned b0, unsigned b1) {
    asm volatile(
        "mma.sync.aligned.m16n8k16.row.col.f32.f16.f16.f32 "
        "{%0,%1,%2,%3}, {%4,%5,%6,%7}, {%8,%9}, {%0,%1,%2,%3};\n"
        : "+f"(c0), "+f"(c1), "+f"(c2), "+f"(c3)
        : "r"(a0), "r"(a1), "r"(a2), "r"(a3), "r"(b0), "r"(b1));
}

__device__ __forceinline__ void ldsm_x4(unsigned& r0, unsigned& r1, unsigned& r2, unsigned& r3,
                                        const half* p) {
    unsigned a = (unsigned)__cvta_generic_to_shared(p);
    asm volatile("ldmatrix.sync.aligned.m8n8.x4.shared.b16 {%0,%1,%2,%3}, [%4];\n"
                 : "=r"(r0), "=r"(r1), "=r"(r2), "=r"(r3) : "r"(a));
}

__device__ __forceinline__ void ldsm_x4_t(unsigned& r0, unsigned& r1, unsigned& r2, unsigned& r3,
                                          const half* p) {
    unsigned a = (unsigned)__cvta_generic_to_shared(p);
    asm volatile("ldmatrix.sync.aligned.m8n8.x4.trans.shared.b16 {%0,%1,%2,%3}, [%4];\n"
                 : "=r"(r0), "=r"(r1), "=r"(r2), "=r"(r3) : "r"(a));
}

__device__ __forceinline__ unsigned pack2(float x, float y) {
    half2 t = __floats2half2_rn(x, y);
    return *reinterpret_cast<unsigned*>(&t);
}

// ---------------------------------------------------------------------------
// Kernel 1: causal flash attention (fp16 HMMA via ldmatrix, fp32 accum).
// grid (S/128, NH, B), 256 threads (8 warps). Warp w owns q rows [16w,16w+16).
// Double-buffered 128-key K/V tiles; per-warp full-tile causal skip.
// ---------------------------------------------------------------------------
__global__ void __launch_bounds__(256, 1) flash_fwd(
    const float* __restrict__ q, const float* __restrict__ k,
    const float* __restrict__ v, float* __restrict__ out)
{
    extern __shared__ __align__(16) half sm[];
    half* Qs   = sm;                 // BQ x PIT
    half* Kbuf = sm + BQ*PIT;        // 2 x (K[BK x PIT] then V[BK x PIT])

    const int qi   = blockIdx.x;
    const int h    = blockIdx.y;
    const int b    = blockIdx.z;
    const int hk   = h >> 2;
    const int tid  = threadIdx.x;
    const int w    = tid >> 5;
    const int lane = tid & 31;
    const int q0   = qi * BQ;

    // ---- Q tile -> smem (scale*log2e folded, fp16 round) ----
    {
        const float* qbase = q + (size_t)(b*S_LEN + q0)*QSTRIDE + h*HD;
        #pragma unroll 4
        for (int i = tid; i < BQ*32; i += 256) {
            int r = i >> 5, c4 = i & 31;
            float4 t = *(const float4*)(qbase + (size_t)r*QSTRIDE + c4*4);
            half2 h0 = __floats2half2_rn(t.x*QSC, t.y*QSC);
            half2 h1 = __floats2half2_rn(t.z*QSC, t.w*QSC);
            *(uint2*)&Qs[r*PIT + c4*4] = make_uint2(*(unsigned*)&h0, *(unsigned*)&h1);
        }
    }

    const float* kb0 = k + (size_t)(b*S_LEN)*KSTRIDE + hk*HD;
    const float* vb0 = v + (size_t)(b*S_LEN)*KSTRIDE + hk*HD;

    // ---- K/V tile 0 -> buf 0 ----
    {
        half* Ks = Kbuf;
        half* Vs = Kbuf + BK*PIT;
        #pragma unroll 4
        for (int i = tid; i < BK*32; i += 256) {
            int r = i >> 5, c4 = i & 31;
            float4 t = *(const float4*)(kb0 + (size_t)r*KSTRIDE + c4*4);
            half2 h0 = __floats2half2_rn(t.x, t.y), h1 = __floats2half2_rn(t.z, t.w);
            *(uint2*)&Ks[r*PIT + c4*4] = make_uint2(*(unsigned*)&h0, *(unsigned*)&h1);
            float4 s = *(const float4*)(vb0 + (size_t)r*KSTRIDE + c4*4);
            half2 g0 = __floats2half2_rn(s.x, s.y), g1 = __floats2half2_rn(s.z, s.w);
            *(uint2*)&Vs[r*PIT + c4*4] = make_uint2(*(unsigned*)&g0, *(unsigned*)&g1);
        }
    }
    __syncthreads();

    // ---- Q fragments, register resident for the whole CTA lifetime ----
    unsigned aq[8][4];
    {
        const half* qp = &Qs[(w*16 + ((lane>>3)&1)*8 + (lane&7))*PIT + (lane>>4)*8];
        #pragma unroll
        for (int kd = 0; kd < 8; kd++)
            ldsm_x4(aq[kd][0], aq[kd][1], aq[kd][2], aq[kd][3], qp + kd*16);
    }

    const int rq  = lane >> 2;
    const int cq  = (lane & 3) * 2;
    const int qg0 = q0 + w*16 + rq;
    const int qg1 = qg0 + 8;

    float m0 = -1e30f, m1 = -1e30f, l0 = 0.f, l1 = 0.f;
    float oacc[16][4];
    #pragma unroll
    for (int nb = 0; nb < 16; nb++) {
        oacc[nb][0] = 0.f; oacc[nb][1] = 0.f; oacc[nb][2] = 0.f; oacc[nb][3] = 0.f;
    }

    const int ntiles = qi + 1;
    int cur = 0;
    for (int jt = 0; jt < ntiles; jt++) {
        const int k0 = jt * BK;
        half* Ks = Kbuf + cur*(2*BK*PIT);
        half* Vs = Ks + BK*PIT;

        // prefetch next tile into the other buffer (overlaps with compute)
        if (jt + 1 < ntiles) {
            half* Kn = Kbuf + (cur^1)*(2*BK*PIT);
            half* Vn = Kn + BK*PIT;
            const float* kbn = kb0 + (size_t)(jt+1)*BK*KSTRIDE;
            const float* vbn = vb0 + (size_t)(jt+1)*BK*KSTRIDE;
            #pragma unroll 4
            for (int i = tid; i < BK*32; i += 256) {
                int r = i >> 5, c4 = i & 31;
                float4 t = *(const float4*)(kbn + (size_t)r*KSTRIDE + c4*4);
                half2 h0 = __floats2half2_rn(t.x, t.y), h1 = __floats2half2_rn(t.z, t.w);
                *(uint2*)&Kn[r*PIT + c4*4] = make_uint2(*(unsigned*)&h0, *(unsigned*)&h1);
                float4 s = *(const float4*)(vbn + (size_t)r*KSTRIDE + c4*4);
                half2 g0 = __floats2half2_rn(s.x, s.y), g1 = __floats2half2_rn(s.z, s.w);
                *(uint2*)&Vn[r*PIT + c4*4] = make_uint2(*(unsigned*)&g0, *(unsigned*)&g1);
            }
        }

        // per-warp full-tile causal skip
        if (k0 <= q0 + w*16 + 15) {
            // ---- S = Q K^T ----
            float sacc[16][4];
            #pragma unroll
            for (int nb = 0; nb < 16; nb++) {
                sacc[nb][0] = 0.f; sacc[nb][1] = 0.f; sacc[nb][2] = 0.f; sacc[nb][3] = 0.f;
            }
            const half* kp = Ks + ((lane>>4)*8 + (lane&7))*PIT + ((lane>>3)&1)*8;
            #pragma unroll
            for (int kd = 0; kd < 8; kd++) {
                #pragma unroll
                for (int nbp = 0; nbp < 8; nbp++) {
                    unsigned b0, b1, b2, b3;
                    ldsm_x4(b0, b1, b2, b3, kp + nbp*16*PIT + kd*16);
                    mma16816(sacc[2*nbp  ][0], sacc[2*nbp  ][1], sacc[2*nbp  ][2], sacc[2*nbp  ][3],
                             aq[kd][0], aq[kd][1], aq[kd][2], aq[kd][3], b0, b1);
                    mma16816(sacc[2*nbp+1][0], sacc[2*nbp+1][1], sacc[2*nbp+1][2], sacc[2*nbp+1][3],
                             aq[kd][0], aq[kd][1], aq[kd][2], aq[kd][3], b2, b3);
                }
            }

            // ---- causal mask (only partially-visible tiles) ----
            if (k0 + BK - 1 > q0 + w*16) {
                #pragma unroll
                for (int nb = 0; nb < 16; nb++) {
                    int c = k0 + nb*8 + cq;
                    if (c     > qg0) sacc[nb][0] = -1e30f;
                    if (c + 1 > qg0) sacc[nb][1] = -1e30f;
                    if (c     > qg1) sacc[nb][2] = -1e30f;
                    if (c + 1 > qg1) sacc[nb][3] = -1e30f;
                }
            }

            // ---- online softmax (log2 domain) ----
            float mx0 = -1e30f, mx1 = -1e30f;
            #pragma unroll
            for (int nb = 0; nb < 16; nb++) {
                mx0 = fmaxf(mx0, fmaxf(sacc[nb][0], sacc[nb][1]));
                mx1 = fmaxf(mx1, fmaxf(sacc[nb][2], sacc[nb][3]));
            }
            mx0 = fmaxf(mx0, __shfl_xor_sync(0xffffffffu, mx0, 1));
            mx0 = fmaxf(mx0, __shfl_xor_sync(0xffffffffu, mx0, 2));
            mx1 = fmaxf(mx1, __shfl_xor_sync(0xffffffffu, mx1, 1));
            mx1 = fmaxf(mx1, __shfl_xor_sync(0xffffffffu, mx1, 2));

            float mn0 = fmaxf(m0, mx0), mn1 = fmaxf(m1, mx1);
            float al0 = exp2f(m0 - mn0), al1 = exp2f(m1 - mn1);
            m0 = mn0; m1 = mn1;

            float s0 = 0.f, s1 = 0.f;
            #pragma unroll
            for (int nb = 0; nb < 16; nb++) {
                sacc[nb][0] = exp2f(sacc[nb][0] - mn0);
                sacc[nb][1] = exp2f(sacc[nb][1] - mn0);
                sacc[nb][2] = exp2f(sacc[nb][2] - mn1);
                sacc[nb][3] = exp2f(sacc[nb][3] - mn1);
                s0 += sacc[nb][0] + sacc[nb][1];
                s1 += sacc[nb][2] + sacc[nb][3];
            }
            s0 += __shfl_xor_sync(0xffffffffu, s0, 1);
            s0 += __shfl_xor_sync(0xffffffffu, s0, 2);
            s1 += __shfl_xor_sync(0xffffffffu, s1, 1);
            s1 += __shfl_xor_sync(0xffffffffu, s1, 2);
            l0 = l0*al0 + s0;
            l1 = l1*al1 + s1;

            #pragma unroll
            for (int nb = 0; nb < 16; nb++) {
                oacc[nb][0] *= al0; oacc[nb][1] *= al0;
                oacc[nb][2] *= al1; oacc[nb][3] *= al1;
            }

            // ---- O += P V (ldmatrix.trans on row-major V) ----
            const half* vp = Vs + (((lane>>3)&1)*8 + (lane&7))*PIT + (lane>>4)*8;
            #pragma unroll
            for (int kb = 0; kb < 8; kb++) {
                unsigned a0 = pack2(sacc[2*kb  ][0], sacc[2*kb  ][1]);
                unsigned a1 = pack2(sacc[2*kb  ][2], sacc[2*kb  ][3]);
                unsigned a2 = pack2(sacc[2*kb+1][0], sacc[2*kb+1][1]);
                unsigned a3 = pack2(sacc[2*kb+1][2], sacc[2*kb+1][3]);
                #pragma unroll
                for (int nbp = 0; nbp < 8; nbp++) {
                    unsigned b0, b1, b2, b3;
                    ldsm_x4_t(b0, b1, b2, b3, vp + kb*16*PIT + nbp*16);
                    mma16816(oacc[2*nbp  ][0], oacc[2*nbp  ][1], oacc[2*nbp  ][2], oacc[2*nbp  ][3],
                             a0, a1, a2, a3, b0, b1);
                    mma16816(oacc[2*nbp+1][0], oacc[2*nbp+1][1], oacc[2*nbp+1][2], oacc[2*nbp+1][3],
                             a0, a1, a2, a3, b2, b3);
                }
            }
        }
        __syncthreads();
        cur ^= 1;
    }

    // ---- epilogue ----
    const float inv0 = 1.0f / l0;
    const float inv1 = 1.0f / l1;
    float* ob0 = out + (size_t)(b*S_LEN + qg0)*QSTRIDE + h*HD;
    float* ob1 = out + (size_t)(b*S_LEN + qg1)*QSTRIDE + h*HD;
    #pragma unroll
    for (int nb = 0; nb < 16; nb++) {
        int col = nb*8 + cq;
        *(float2*)(ob0 + col) = make_float2(oacc[nb][0]*inv0, oacc[nb][1]*inv0);
        *(float2*)(ob1 + col) = make_float2(oacc[nb][2]*inv1, oacc[nb][3]*inv1);
    }

    // stash exact softmax stats (log2-domain m) for the last NTS query rows
    if (q0 == S_LEN - BQ && w >= 4 && (lane & 3) == 0) {
        int base = (b*NH + h)*NTS;
        int r0i  = qg0 - (S_LEN - NTS);
        g_m[base + r0i    ] = m0;
        g_m[base + r0i + 8] = m1;
        g_l[base + r0i    ] = l0;
        g_l[base + r0i + 8] = l1;
    }
}

// ---------------------------------------------------------------------------
// Kernel 2: score_sum[b,h,k] = sum over last 64 queries q>=k of 2^(s-m_q)/l_q.
// Tensor-core version; S values bitwise match kernel 1's mma results.
// grid (S/128, NH, B), 128 threads (4 warps). Warp w: q rows [16w,16w+16).
// ---------------------------------------------------------------------------
__global__ void __launch_bounds__(128, 1) score_sum_k(
    const float* __restrict__ qg, const float* __restrict__ kg,
    float* __restrict__ ssum)
{
    extern __shared__ __align__(16) half sm2[];
    half*  Qs = sm2;                       // 64 x PIT
    half*  Ks = sm2 + 64*PIT;              // 128 x PIT
    float* ms = (float*)(sm2 + (64+128)*PIT);
    float* ws = ms + 64;
    float* part = ws + 64;                 // 4 x 128

    const int tid  = threadIdx.x;
    const int w    = tid >> 5;
    const int lane = tid & 31;
    const int h    = blockIdx.y;
    const int b    = blockIdx.z;
    const int hk   = h >> 2;
    const int k0   = blockIdx.x * 128;

    {
        const float* qbase = qg + (size_t)(b*S_LEN + (S_LEN - NTS))*QSTRIDE + h*HD;
        #pragma unroll 4
        for (int i = tid; i < 64*32; i += 128) {
            int r = i >> 5, c4 = i & 31;
            float4 t = *(const float4*)(qbase + (size_t)r*QSTRIDE + c4*4);
            half2 h0 = __floats2half2_rn(t.x*QSC, t.y*QSC);
            half2 h1 = __floats2half2_rn(t.z*QSC, t.w*QSC);
            *(uint2*)&Qs[r*PIT + c4*4] = make_uint2(*(unsigned*)&h0, *(unsigned*)&h1);
        }
        const float* kbase = kg + (size_t)(b*S_LEN + k0)*KSTRIDE + hk*HD;
        #pragma unroll 4
        for (int i = tid; i < 128*32; i += 128) {
            int r = i >> 5, c4 = i & 31;
            float4 t = *(const float4*)(kbase + (size_t)r*KSTRIDE + c4*4);
            half2 h0 = __floats2half2_rn(t.x, t.y), h1 = __floats2half2_rn(t.z, t.w);
            *(uint2*)&Ks[r*PIT + c4*4] = make_uint2(*(unsigned*)&h0, *(unsigned*)&h1);
        }
        if (tid < 64) {
            int base = (b*NH + h)*NTS;
            ms[tid] = g_m[base + tid];
            ws[tid] = 1.0f / g_l[base + tid];
        }
    }
    __syncthreads();

    unsigned aq[8][4];
    {
        const half* qp = &Qs[(w*16 + ((lane>>3)&1)*8 + (lane&7))*PIT + (lane>>4)*8];
        #pragma unroll
        for (int kd = 0; kd < 8; kd++)
            ldsm_x4(aq[kd][0], aq[kd][1], aq[kd][2], aq[kd][3], qp + kd*16);
    }

    float sacc[16][4];
    #pragma unroll
    for (int nb = 0; nb < 16; nb++) {
        sacc[nb][0] = 0.f; sacc[nb][1] = 0.f; sacc[nb][2] = 0.f; sacc[nb][3] = 0.f;
    }
    {
        const half* kp = Ks + ((lane>>4)*8 + (lane&7))*PIT + ((lane>>3)&1)*8;
        #pragma unroll
        for (int kd = 0; kd < 8; kd++) {
            #pragma unroll
            for (int nbp = 0; nbp < 8; nbp++) {
                unsigned b0, b1, b2, b3;
                ldsm_x4(b0, b1, b2, b3, kp + nbp*16*PIT + kd*16);
                mma16816(sacc[2*nbp  ][0], sacc[2*nbp  ][1], sacc[2*nbp  ][2], sacc[2*nbp  ][3],
                         aq[kd][0], aq[kd][1], aq[kd][2], aq[kd][3], b0, b1);
                mma16816(sacc[2*nbp+1][0], sacc[2*nbp+1][1], sacc[2*nbp+1][2], sacc[2*nbp+1][3],
                         aq[kd][0], aq[kd][1], aq[kd][2], aq[kd][3], b2, b3);
            }
        }
    }

    const int rq = lane >> 2;
    const int cq = (lane & 3) * 2;
    const float m0 = ms[w*16 + rq],     m1 = ms[w*16 + rq + 8];
    const float w0 = ws[w*16 + rq],     w1 = ws[w*16 + rq + 8];
    const int  qg0 = S_LEN - NTS + w*16 + rq, qg1 = qg0 + 8;

    #pragma unroll
    for (int nb = 0; nb < 16; nb++) {
        int c = k0 + nb*8 + cq;
        float e0 = (c     <= qg0) ? exp2f(sacc[nb][0] - m0) * w0 : 0.f;
        float e1 = (c + 1 <= qg0) ? exp2f(sacc[nb][1] - m0) * w0 : 0.f;
        float e2 = (c     <= qg1) ? exp2f(sacc[nb][2] - m1) * w1 : 0.f;
        float e3 = (c + 1 <= qg1) ? exp2f(sacc[nb][3] - m1) * w1 : 0.f;
        float cs0 = e0 + e2, cs1 = e1 + e3;
        cs0 += __shfl_xor_sync(0xffffffffu, cs0, 4);
        cs0 += __shfl_xor_sync(0xffffffffu, cs0, 8);
        cs0 += __shfl_xor_sync(0xffffffffu, cs0, 16);
        cs1 += __shfl_xor_sync(0xffffffffu, cs1, 4);
        cs1 += __shfl_xor_sync(0xffffffffu, cs1, 8);
        cs1 += __shfl_xor_sync(0xffffffffu, cs1, 16);
        if (lane < 4) {
            part[w*128 + nb*8 + cq    ] = cs0;
            part[w*128 + nb*8 + cq + 1] = cs1;
        }
    }
    __syncthreads();

    float s = part[tid] + part[128 + tid] + part[256 + tid] + part[384 + tid];
    ssum[((size_t)b*NH + h)*S_LEN + k0 + tid] = s;
}

// ---------------------------------------------------------------------------
extern "C" void kernel_launch(void* const* d_in, const int* in_sizes, int n_in,
                              void* d_out, int out_size)
{
    const float* q = (const float*)d_in[0];
    const float* k = (const float*)d_in[1];
    const float* v = (const float*)d_in[2];

    float* out  = (float*)d_out;
    float* ssum = out + (size_t)B_SZ * S_LEN * QSTRIDE;

    cudaFuncSetAttribute(flash_fwd,   cudaFuncAttributeMaxDynamicSharedMemorySize, SMEM1);
    cudaFuncSetAttribute(score_sum_k, cudaFuncAttributeMaxDynamicSharedMemorySize, SMEM2);

    dim3 g1(S_LEN/BQ, NH, B_SZ);
    flash_fwd<<<g1, 256, SMEM1>>>(q, k, v, out);

    dim3 g2(S_LEN/128, NH, B_SZ);
    score_sum_k<<<g2, 128, SMEM2>>>(q, k, ssum);
}

// round 3
// speedup vs baseline: 2.3999x; 1.0590x over previous
#include <cuda_runtime.h>
#include <cuda_fp16.h>

#define S_LEN 2048
#define B_SZ 2
#define NH 16
#define NKV 4
#define HD 128
#define QSTRIDE (NH*HD)      /* 2048 */
#define KSTRIDE (NKV*HD)     /* 512  */
#define SCALE_F 0.08838834764831845f
#define LOG2E   1.44269504088896341f
#define QSC     (SCALE_F*LOG2E)      /* fold softmax scale + log2e into Q */
#define BQ 128
#define BK 128
#define PIT 136              /* smem pitch in halves: 272B rows -> conflict-free LDSM */
#define NTS 64

#define SMEM1 (5*BK*PIT*2)                              /* Q + 2*(K+V) = 174080 B */
#define SMEM2 ((64+128)*PIT*2 + (64+64+512)*4)          /* 54784 B */

__device__ float g_m[B_SZ*NH*NTS];   // log2-domain row max
__device__ float g_l[B_SZ*NH*NTS];   // row denom

__device__ __forceinline__ float ex2f(float x) {
    float y;
    asm("ex2.approx.ftz.f32 %0, %1;" : "=f"(y) : "f"(x));
    return y;
}

__device__ __forceinline__ void mma16816(float& c0, float& c1, float& c2, float& c3,
                                         unsigned a0, unsigned a1, unsigned a2, unsigned a3,
                                         unsigned b0, unsigned b1) {
    asm volatile(
        "mma.sync.aligned.m16n8k16.row.col.f32.f16.f16.f32 "
        "{%0,%1,%2,%3}, {%4,%5,%6,%7}, {%8,%9}, {%0,%1,%2,%3};\n"
        : "+f"(c0), "+f"(c1), "+f"(c2), "+f"(c3)
        : "r"(a0), "r"(a1), "r"(a2), "r"(a3), "r"(b0), "r"(b1));
}

__device__ __forceinline__ void ldsm_x4(unsigned& r0, unsigned& r1, unsigned& r2, unsigned& r3,
                                        const half* p) {
    unsigned a = (unsigned)__cvta_generic_to_shared(p);
    asm volatile("ldmatrix.sync.aligned.m8n8.x4.shared.b16 {%0,%1,%2,%3}, [%4];\n"
                 : "=r"(r0), "=r"(r1), "=r"(r2), "=r"(r3) : "r"(a));
}

__device__ __forceinline__ void ldsm_x4_t(unsigned& r0, unsigned& r1, unsigned& r2, unsigned& r3,
                                          const half* p) {
    unsigned a = (unsigned)__cvta_generic_to_shared(p);
    asm volatile("ldmatrix.sync.aligned.m8n8.x4.trans.shared.b16 {%0,%1,%2,%3}, [%4];\n"
                 : "=r"(r0), "=r"(r1), "=r"(r2), "=r"(r3) : "r"(a));
}

__device__ __forceinline__ unsigned pack2(float x, float y) {
    half2 t = __floats2half2_rn(x, y);
    return *reinterpret_cast<unsigned*>(&t);
}

// ---------------------------------------------------------------------------
// Kernel 1: causal flash attention (fp16 HMMA via ldmatrix, fp32 accum).
// grid (S/128, NH, B), 256 threads (8 warps). Warp w owns q rows [16w,16w+16).
// Double-buffered 128-key K/V tiles; per-warp full-tile causal skip.
// Heavy q-tiles launch first (qi reversed) for LPT-style wave balance.
// ---------------------------------------------------------------------------
__global__ void __launch_bounds__(256, 1) flash_fwd(
    const float* __restrict__ q, const float* __restrict__ k,
    const float* __restrict__ v, float* __restrict__ out)
{
    extern __shared__ __align__(16) half sm[];
    half* Qs   = sm;                 // BQ x PIT
    half* Kbuf = sm + BQ*PIT;        // 2 x (K[BK x PIT] then V[BK x PIT])

    const int qi   = gridDim.x - 1 - blockIdx.x;   // heavy tiles first
    const int h    = blockIdx.y;
    const int b    = blockIdx.z;
    const int hk   = h >> 2;
    const int tid  = threadIdx.x;
    const int w    = tid >> 5;
    const int lane = tid & 31;
    const int q0   = qi * BQ;

    // ---- Q tile -> smem (scale*log2e folded, fp16 round) ----
    {
        const float* qbase = q + (size_t)(b*S_LEN + q0)*QSTRIDE + h*HD;
        #pragma unroll 4
        for (int i = tid; i < BQ*32; i += 256) {
            int r = i >> 5, c4 = i & 31;
            float4 t = *(const float4*)(qbase + (size_t)r*QSTRIDE + c4*4);
            half2 h0 = __floats2half2_rn(t.x*QSC, t.y*QSC);
            half2 h1 = __floats2half2_rn(t.z*QSC, t.w*QSC);
            *(uint2*)&Qs[r*PIT + c4*4] = make_uint2(*(unsigned*)&h0, *(unsigned*)&h1);
        }
    }

    const float* kb0 = k + (size_t)(b*S_LEN)*KSTRIDE + hk*HD;
    const float* vb0 = v + (size_t)(b*S_LEN)*KSTRIDE + hk*HD;

    // ---- K/V tile 0 -> buf 0 ----
    {
        half* Ks = Kbuf;
        half* Vs = Kbuf + BK*PIT;
        #pragma unroll 4
        for (int i = tid; i < BK*32; i += 256) {
            int r = i >> 5, c4 = i & 31;
            float4 t = *(const float4*)(kb0 + (size_t)r*KSTRIDE + c4*4);
            half2 h0 = __floats2half2_rn(t.x, t.y), h1 = __floats2half2_rn(t.z, t.w);
            *(uint2*)&Ks[r*PIT + c4*4] = make_uint2(*(unsigned*)&h0, *(unsigned*)&h1);
            float4 s = *(const float4*)(vb0 + (size_t)r*KSTRIDE + c4*4);
            half2 g0 = __floats2half2_rn(s.x, s.y), g1 = __floats2half2_rn(s.z, s.w);
            *(uint2*)&Vs[r*PIT + c4*4] = make_uint2(*(unsigned*)&g0, *(unsigned*)&g1);
        }
    }
    __syncthreads();

    // ---- Q fragments, register resident for the whole CTA lifetime ----
    unsigned aq[8][4];
    {
        const half* qp = &Qs[(w*16 + ((lane>>3)&1)*8 + (lane&7))*PIT + (lane>>4)*8];
        #pragma unroll
        for (int kd = 0; kd < 8; kd++)
            ldsm_x4(aq[kd][0], aq[kd][1], aq[kd][2], aq[kd][3], qp + kd*16);
    }

    const int rq  = lane >> 2;
    const int cq  = (lane & 3) * 2;
    const int qg0 = q0 + w*16 + rq;
    const int qg1 = qg0 + 8;

    float m0 = -1e30f, m1 = -1e30f, l0 = 0.f, l1 = 0.f;
    float oacc[16][4];
    #pragma unroll
    for (int nb = 0; nb < 16; nb++) {
        oacc[nb][0] = 0.f; oacc[nb][1] = 0.f; oacc[nb][2] = 0.f; oacc[nb][3] = 0.f;
    }

    const int ntiles = qi + 1;
    int cur = 0;
    for (int jt = 0; jt < ntiles; jt++) {
        const int k0 = jt * BK;
        half* Ks = Kbuf + cur*(2*BK*PIT);
        half* Vs = Ks + BK*PIT;

        // prefetch next tile into the other buffer (overlaps with compute)
        if (jt + 1 < ntiles) {
            half* Kn = Kbuf + (cur^1)*(2*BK*PIT);
            half* Vn = Kn + BK*PIT;
            const float* kbn = kb0 + (size_t)(jt+1)*BK*KSTRIDE;
            const float* vbn = vb0 + (size_t)(jt+1)*BK*KSTRIDE;
            #pragma unroll 4
            for (int i = tid; i < BK*32; i += 256) {
                int r = i >> 5, c4 = i & 31;
                float4 t = *(const float4*)(kbn + (size_t)r*KSTRIDE + c4*4);
                half2 h0 = __floats2half2_rn(t.x, t.y), h1 = __floats2half2_rn(t.z, t.w);
                *(uint2*)&Kn[r*PIT + c4*4] = make_uint2(*(unsigned*)&h0, *(unsigned*)&h1);
                float4 s = *(const float4*)(vbn + (size_t)r*KSTRIDE + c4*4);
                half2 g0 = __floats2half2_rn(s.x, s.y), g1 = __floats2half2_rn(s.z, s.w);
                *(uint2*)&Vn[r*PIT + c4*4] = make_uint2(*(unsigned*)&g0, *(unsigned*)&g1);
            }
        }

        // per-warp full-tile causal skip
        if (k0 <= q0 + w*16 + 15) {
            // ---- S = Q K^T ----
            float sacc[16][4];
            #pragma unroll
            for (int nb = 0; nb < 16; nb++) {
                sacc[nb][0] = 0.f; sacc[nb][1] = 0.f; sacc[nb][2] = 0.f; sacc[nb][3] = 0.f;
            }
            const half* kp = Ks + ((lane>>4)*8 + (lane&7))*PIT + ((lane>>3)&1)*8;
            #pragma unroll
            for (int kd = 0; kd < 8; kd++) {
                #pragma unroll
                for (int nbp = 0; nbp < 8; nbp++) {
                    unsigned b0, b1, b2, b3;
                    ldsm_x4(b0, b1, b2, b3, kp + nbp*16*PIT + kd*16);
                    mma16816(sacc[2*nbp  ][0], sacc[2*nbp  ][1], sacc[2*nbp  ][2], sacc[2*nbp  ][3],
                             aq[kd][0], aq[kd][1], aq[kd][2], aq[kd][3], b0, b1);
                    mma16816(sacc[2*nbp+1][0], sacc[2*nbp+1][1], sacc[2*nbp+1][2], sacc[2*nbp+1][3],
                             aq[kd][0], aq[kd][1], aq[kd][2], aq[kd][3], b2, b3);
                }
            }

            // ---- causal mask (only partially-visible tiles) ----
            if (k0 + BK - 1 > q0 + w*16) {
                #pragma unroll
                for (int nb = 0; nb < 16; nb++) {
                    int c = k0 + nb*8 + cq;
                    if (c     > qg0) sacc[nb][0] = -1e30f;
                    if (c + 1 > qg0) sacc[nb][1] = -1e30f;
                    if (c     > qg1) sacc[nb][2] = -1e30f;
                    if (c + 1 > qg1) sacc[nb][3] = -1e30f;
                }
            }

            // ---- online softmax (log2 domain, MUFU.EX2) ----
            float mx0 = -1e30f, mx1 = -1e30f;
            #pragma unroll
            for (int nb = 0; nb < 16; nb++) {
                mx0 = fmaxf(mx0, fmaxf(sacc[nb][0], sacc[nb][1]));
                mx1 = fmaxf(mx1, fmaxf(sacc[nb][2], sacc[nb][3]));
            }
            mx0 = fmaxf(mx0, __shfl_xor_sync(0xffffffffu, mx0, 1));
            mx0 = fmaxf(mx0, __shfl_xor_sync(0xffffffffu, mx0, 2));
            mx1 = fmaxf(mx1, __shfl_xor_sync(0xffffffffu, mx1, 1));
            mx1 = fmaxf(mx1, __shfl_xor_sync(0xffffffffu, mx1, 2));

            float mn0 = fmaxf(m0, mx0), mn1 = fmaxf(m1, mx1);
            float al0 = ex2f(m0 - mn0), al1 = ex2f(m1 - mn1);
            m0 = mn0; m1 = mn1;

            float s0 = 0.f, s1 = 0.f;
            #pragma unroll
            for (int nb = 0; nb < 16; nb++) {
                sacc[nb][0] = ex2f(sacc[nb][0] - mn0);
                sacc[nb][1] = ex2f(sacc[nb][1] - mn0);
                sacc[nb][2] = ex2f(sacc[nb][2] - mn1);
                sacc[nb][3] = ex2f(sacc[nb][3] - mn1);
                s0 += sacc[nb][0] + sacc[nb][1];
                s1 += sacc[nb][2] + sacc[nb][3];
            }
            s0 += __shfl_xor_sync(0xffffffffu, s0, 1);
            s0 += __shfl_xor_sync(0xffffffffu, s0, 2);
            s1 += __shfl_xor_sync(0xffffffffu, s1, 1);
            s1 += __shfl_xor_sync(0xffffffffu, s1, 2);
            l0 = l0*al0 + s0;
            l1 = l1*al1 + s1;

            #pragma unroll
            for (int nb = 0; nb < 16; nb++) {
                oacc[nb][0] *= al0; oacc[nb][1] *= al0;
                oacc[nb][2] *= al1; oacc[nb][3] *= al1;
            }

            // ---- O += P V (ldmatrix.trans on row-major V) ----
            const half* vp = Vs + (((lane>>3)&1)*8 + (lane&7))*PIT + (lane>>4)*8;
            #pragma unroll
            for (int kb = 0; kb < 8; kb++) {
                unsigned a0 = pack2(sacc[2*kb  ][0], sacc[2*kb  ][1]);
                unsigned a1 = pack2(sacc[2*kb  ][2], sacc[2*kb  ][3]);
                unsigned a2 = pack2(sacc[2*kb+1][0], sacc[2*kb+1][1]);
                unsigned a3 = pack2(sacc[2*kb+1][2], sacc[2*kb+1][3]);
                #pragma unroll
                for (int nbp = 0; nbp < 8; nbp++) {
                    unsigned b0, b1, b2, b3;
                    ldsm_x4_t(b0, b1, b2, b3, vp + kb*16*PIT + nbp*16);
                    mma16816(oacc[2*nbp  ][0], oacc[2*nbp  ][1], oacc[2*nbp  ][2], oacc[2*nbp  ][3],
                             a0, a1, a2, a3, b0, b1);
                    mma16816(oacc[2*nbp+1][0], oacc[2*nbp+1][1], oacc[2*nbp+1][2], oacc[2*nbp+1][3],
                             a0, a1, a2, a3, b2, b3);
                }
            }
        }
        __syncthreads();
        cur ^= 1;
    }

    // ---- epilogue ----
    const float inv0 = 1.0f / l0;
    const float inv1 = 1.0f / l1;
    float* ob0 = out + (size_t)(b*S_LEN + qg0)*QSTRIDE + h*HD;
    float* ob1 = out + (size_t)(b*S_LEN + qg1)*QSTRIDE + h*HD;
    #pragma unroll
    for (int nb = 0; nb < 16; nb++) {
        int col = nb*8 + cq;
        *(float2*)(ob0 + col) = make_float2(oacc[nb][0]*inv0, oacc[nb][1]*inv0);
        *(float2*)(ob1 + col) = make_float2(oacc[nb][2]*inv1, oacc[nb][3]*inv1);
    }

    // stash exact softmax stats (log2-domain m) for the last NTS query rows
    if (q0 == S_LEN - BQ && w >= 4 && (lane & 3) == 0) {
        int base = (b*NH + h)*NTS;
        int r0i  = qg0 - (S_LEN - NTS);
        g_m[base + r0i    ] = m0;
        g_m[base + r0i + 8] = m1;
        g_l[base + r0i    ] = l0;
        g_l[base + r0i + 8] = l1;
    }
}

// ---------------------------------------------------------------------------
// Kernel 2: score_sum[b,h,k] = sum over last 64 queries q>=k of 2^(s-m_q)/l_q.
// Tensor-core version; S values bitwise match kernel 1's mma results.
// grid (S/128, NH, B), 128 threads (4 warps). Warp w: q rows [16w,16w+16).
// ---------------------------------------------------------------------------
__global__ void __launch_bounds__(128, 1) score_sum_k(
    const float* __restrict__ qg, const float* __restrict__ kg,
    float* __restrict__ ssum)
{
    extern __shared__ __align__(16) half sm2[];
    half*  Qs = sm2;                       // 64 x PIT
    half*  Ks = sm2 + 64*PIT;              // 128 x PIT
    float* ms = (float*)(sm2 + (64+128)*PIT);
    float* ws = ms + 64;
    float* part = ws + 64;                 // 4 x 128

    const int tid  = threadIdx.x;
    const int w    = tid >> 5;
    const int lane = tid & 31;
    const int h    = blockIdx.y;
    const int b    = blockIdx.z;
    const int hk   = h >> 2;
    const int k0   = blockIdx.x * 128;

    {
        const float* qbase = qg + (size_t)(b*S_LEN + (S_LEN - NTS))*QSTRIDE + h*HD;
        #pragma unroll 4
        for (int i = tid; i < 64*32; i += 128) {
            int r = i >> 5, c4 = i & 31;
            float4 t = *(const float4*)(qbase + (size_t)r*QSTRIDE + c4*4);
            half2 h0 = __floats2half2_rn(t.x*QSC, t.y*QSC);
            half2 h1 = __floats2half2_rn(t.z*QSC, t.w*QSC);
            *(uint2*)&Qs[r*PIT + c4*4] = make_uint2(*(unsigned*)&h0, *(unsigned*)&h1);
        }
        const float* kbase = kg + (size_t)(b*S_LEN + k0)*KSTRIDE + hk*HD;
        #pragma unroll 4
        for (int i = tid; i < 128*32; i += 128) {
            int r = i >> 5, c4 = i & 31;
            float4 t = *(const float4*)(kbase + (size_t)r*KSTRIDE + c4*4);
            half2 h0 = __floats2half2_rn(t.x, t.y), h1 = __floats2half2_rn(t.z, t.w);
            *(uint2*)&Ks[r*PIT + c4*4] = make_uint2(*(unsigned*)&h0, *(unsigned*)&h1);
        }
        if (tid < 64) {
            int base = (b*NH + h)*NTS;
            ms[tid] = g_m[base + tid];
            ws[tid] = 1.0f / g_l[base + tid];
        }
    }
    __syncthreads();

    unsigned aq[8][4];
    {
        const half* qp = &Qs[(w*16 + ((lane>>3)&1)*8 + (lane&7))*PIT + (lane>>4)*8];
        #pragma unroll
        for (int kd = 0; kd < 8; kd++)
            ldsm_x4(aq[kd][0], aq[kd][1], aq[kd][2], aq[kd][3], qp + kd*16);
    }

    float sacc[16][4];
    #pragma unroll
    for (int nb = 0; nb < 16; nb++) {
        sacc[nb][0] = 0.f; sacc[nb][1] = 0.f; sacc[nb][2] = 0.f; sacc[nb][3] = 0.f;
    }
    {
        const half* kp = Ks + ((lane>>4)*8 + (lane&7))*PIT + ((lane>>3)&1)*8;
        #pragma unroll
        for (int kd = 0; kd < 8; kd++) {
            #pragma unroll
            for (int nbp = 0; nbp < 8; nbp++) {
                unsigned b0, b1, b2, b3;
                ldsm_x4(b0, b1, b2, b3, kp + nbp*16*PIT + kd*16);
                mma16816(sacc[2*nbp  ][0], sacc[2*nbp  ][1], sacc[2*nbp  ][2], sacc[2*nbp  ][3],
                         aq[kd][0], aq[kd][1], aq[kd][2], aq[kd][3], b0, b1);
                mma16816(sacc[2*nbp+1][0], sacc[2*nbp+1][1], sacc[2*nbp+1][2], sacc[2*nbp+1][3],
                         aq[kd][0], aq[kd][1], aq[kd][2], aq[kd][3], b2, b3);
            }
        }
    }

    const int rq = lane >> 2;
    const int cq = (lane & 3) * 2;
    const float m0 = ms[w*16 + rq],     m1 = ms[w*16 + rq + 8];
    const float w0 = ws[w*16 + rq],     w1 = ws[w*16 + rq + 8];
    const int  qg0 = S_LEN - NTS + w*16 + rq, qg1 = qg0 + 8;

    #pragma unroll
    for (int nb = 0; nb < 16; nb++) {
        int c = k0 + nb*8 + cq;
        float e0 = (c     <= qg0) ? ex2f(sacc[nb][0] - m0) * w0 : 0.f;
        float e1 = (c + 1 <= qg0) ? ex2f(sacc[nb][1] - m0) * w0 : 0.f;
        float e2 = (c     <= qg1) ? ex2f(sacc[nb][2] - m1) * w1 : 0.f;
        float e3 = (c + 1 <= qg1) ? ex2f(sacc[nb][3] - m1) * w1 : 0.f;
        float cs0 = e0 + e2, cs1 = e1 + e3;
        cs0 += __shfl_xor_sync(0xffffffffu, cs0, 4);
        cs0 += __shfl_xor_sync(0xffffffffu, cs0, 8);
        cs0 += __shfl_xor_sync(0xffffffffu, cs0, 16);
        cs1 += __shfl_xor_sync(0xffffffffu, cs1, 4);
        cs1 += __shfl_xor_sync(0xffffffffu, cs1, 8);
        cs1 += __shfl_xor_sync(0xffffffffu, cs1, 16);
        if (lane < 4) {
            part[w*128 + nb*8 + cq    ] = cs0;
            part[w*128 + nb*8 + cq + 1] = cs1;
        }
    }
    __syncthreads();

    float s = part[tid] + part[128 + tid] + part[256 + tid] + part[384 + tid];
    ssum[((size_t)b*NH + h)*S_LEN + k0 + tid] = s;
}

// ---------------------------------------------------------------------------
extern "C" void kernel_launch(void* const* d_in, const int* in_sizes, int n_in,
                              void* d_out, int out_size)
{
    const float* q = (const float*)d_in[0];
    const float* k = (const float*)d_in[1];
    const float* v = (const float*)d_in[2];

    float* out  = (float*)d_out;
    float* ssum = out + (size_t)B_SZ * S_LEN * QSTRIDE;

    cudaFuncSetAttribute(flash_fwd,   cudaFuncAttributeMaxDynamicSharedMemorySize, SMEM1);
    cudaFuncSetAttribute(score_sum_k, cudaFuncAttributeMaxDynamicSharedMemorySize, SMEM2);

    dim3 g1(S_LEN/BQ, NH, B_SZ);
    flash_fwd<<<g1, 256, SMEM1>>>(q, k, v, out);

    dim3 g2(S_LEN/128, NH, B_SZ);
    score_sum_k<<<g2, 128, SMEM2>>>(q, k, ssum);
}